// round 2
// baseline (speedup 1.0000x reference)
#include <cuda_runtime.h>
#include <math_constants.h>

#define BATCH 2
#define SEQ 2048
#define DMODEL 1024
#define NHEADS 16
#define HDIM 64
#define ROWS (BATCH*SEQ)   // 4096

// Scratch (allocation-free rule: __device__ globals). 16 MB each.
__device__ float g_q[(size_t)ROWS * DMODEL];
__device__ float g_k[(size_t)ROWS * DMODEL];
__device__ float g_v[(size_t)ROWS * DMODEL];
__device__ float g_att[(size_t)ROWS * DMODEL];

// ---------------------------------------------------------------------------
// SGEMM_NT tile body: C[crow0:+128, ccol0:+128] = A[M,K] * B[N,K]^T
// BM=BN=128, BK=16, TM=TN=8, 256 threads. All dims multiples of tile sizes.
// ---------------------------------------------------------------------------
__device__ __forceinline__ void gemm_tile_128(
    const float* __restrict__ A, const float* __restrict__ Bw,
    float* __restrict__ C, int crow0, int ccol0, int N, int K)
{
    constexpr int BM = 128, BN = 128, BK = 16, TM = 8, TN = 8;
    __shared__ float As[BK][BM];
    __shared__ float Bs[BK][BN];

    const int tid  = threadIdx.x;
    const int trow = (tid >> 4) * TM;   // 0..120
    const int tcol = (tid & 15) * TN;   // 0..120
    const int lrow = tid >> 2;          // 0..63
    const int lcol = (tid & 3) * 4;     // 0,4,8,12

    float acc[TM][TN] = {};
    float ar[TM], br[TN];

    for (int k0 = 0; k0 < K; k0 += BK) {
        #pragma unroll
        for (int p = 0; p < 2; p++) {
            const int r = lrow + p * 64;
            float4 av = *reinterpret_cast<const float4*>(
                &A[(size_t)(crow0 + r) * K + k0 + lcol]);
            As[lcol + 0][r] = av.x; As[lcol + 1][r] = av.y;
            As[lcol + 2][r] = av.z; As[lcol + 3][r] = av.w;
            float4 bv = *reinterpret_cast<const float4*>(
                &Bw[(size_t)(ccol0 + r) * K + k0 + lcol]);
            Bs[lcol + 0][r] = bv.x; Bs[lcol + 1][r] = bv.y;
            Bs[lcol + 2][r] = bv.z; Bs[lcol + 3][r] = bv.w;
        }
        __syncthreads();
        #pragma unroll
        for (int kk = 0; kk < BK; kk++) {
            #pragma unroll
            for (int i = 0; i < TM; i++) ar[i] = As[kk][trow + i];
            #pragma unroll
            for (int j = 0; j < TN; j++) br[j] = Bs[kk][tcol + j];
            #pragma unroll
            for (int i = 0; i < TM; i++)
                #pragma unroll
                for (int j = 0; j < TN; j++)
                    acc[i][j] += ar[i] * br[j];
        }
        __syncthreads();
    }

    #pragma unroll
    for (int i = 0; i < TM; i++) {
        const size_t off = (size_t)(crow0 + trow + i) * N + ccol0 + tcol;
        *reinterpret_cast<float4*>(&C[off]) =
            make_float4(acc[i][0], acc[i][1], acc[i][2], acc[i][3]);
        *reinterpret_cast<float4*>(&C[off + 4]) =
            make_float4(acc[i][4], acc[i][5], acc[i][6], acc[i][7]);
    }
}

// Fused QKV: grid.x = 24 (3 weights x 8 col tiles), grid.y = 32 (row tiles)
__global__ __launch_bounds__(256) void qkv_gemm_kernel(
    const float* __restrict__ x,
    const float* __restrict__ Wq,
    const float* __restrict__ Wk,
    const float* __restrict__ Wv)
{
    const int g  = blockIdx.x >> 3;
    const int bx = blockIdx.x & 7;
    const float* W; float* C;
    if      (g == 0) { W = Wq; C = g_q; }
    else if (g == 1) { W = Wk; C = g_k; }
    else             { W = Wv; C = g_v; }
    gemm_tile_128(x, W, C, blockIdx.y * 128, bx * 128, DMODEL, DMODEL);
}

__global__ __launch_bounds__(256) void out_gemm_kernel(
    const float* __restrict__ Wo, float* __restrict__ out)
{
    gemm_tile_128(g_att, Wo, out, blockIdx.y * 128, blockIdx.x * 128, DMODEL, DMODEL);
}

// ---------------------------------------------------------------------------
// In-place RoPE on g_q, g_k. Each thread owns one (d, d+32) pair of one head
// of one row -> no read/write hazard. idx layout: [row][head][d<32]
// ---------------------------------------------------------------------------
__global__ __launch_bounds__(256) void rope_kernel(
    const float* __restrict__ cosp, const float* __restrict__ sinp)
{
    const int idx = blockIdx.x * blockDim.x + threadIdx.x;
    const int d   = idx & 31;
    const int h   = (idx >> 5) & (NHEADS - 1);
    const int row = idx >> 9;                  // [0, ROWS)
    const int s   = row & (SEQ - 1);

    const float c1 = cosp[s * HDIM + d];
    const float s1 = sinp[s * HDIM + d];
    const float c2 = cosp[s * HDIM + d + 32];
    const float s2 = sinp[s * HDIM + d + 32];

    const size_t base = (size_t)row * DMODEL + h * HDIM;

    const float q1 = g_q[base + d], q2 = g_q[base + d + 32];
    g_q[base + d]      = q1 * c1 - q2 * s1;   // rotate_half: [-t2, t1]
    g_q[base + d + 32] = q2 * c2 + q1 * s2;

    const float k1 = g_k[base + d], k2 = g_k[base + d + 32];
    g_k[base + d]      = k1 * c1 - k2 * s1;
    g_k[base + d + 32] = k2 * c2 + k1 * s2;
}

// ---------------------------------------------------------------------------
// Causal flash attention. Block = 64 threads, one 64-query tile of one (b,h).
// Each thread owns one query row: q (prescaled by 1/8) and o accumulator in
// registers; K/V 64x64 tiles in smem (all lanes read same address ->
// broadcast, conflict-free). Online softmax over 16-key chunks.
// ---------------------------------------------------------------------------
__global__ __launch_bounds__(64) void attn_kernel()
{
    __shared__ float Ks[64][64];
    __shared__ float Vs[64][64];

    const int qt = blockIdx.x;             // query tile [0,32)
    const int bh = blockIdx.y;             // [0, B*H)
    const int b  = bh >> 4, h = bh & 15;
    const int r  = threadIdx.x;            // query row within tile
    const int qrow = qt * 64 + r;

    float qreg[64];
    {
        const float4* qp = reinterpret_cast<const float4*>(
            &g_q[(size_t)(b * SEQ + qrow) * DMODEL + h * HDIM]);
        #pragma unroll
        for (int i = 0; i < 16; i++) {
            float4 v = qp[i];
            qreg[4*i+0] = v.x * 0.125f; qreg[4*i+1] = v.y * 0.125f;
            qreg[4*i+2] = v.z * 0.125f; qreg[4*i+3] = v.w * 0.125f;
        }
    }

    float o[64];
    #pragma unroll
    for (int d = 0; d < 64; d++) o[d] = 0.f;
    float mval = -CUDART_INF_F, l = 0.f;

    for (int kt = 0; kt <= qt; kt++) {
        const int k0 = kt * 64;
        __syncthreads();
        {   // cooperative K/V tile load: 64 threads x 16 float4 each matrix
            const float4* kp = reinterpret_cast<const float4*>(
                &g_k[(size_t)(b * SEQ + k0) * DMODEL + h * HDIM]);
            const float4* vp = reinterpret_cast<const float4*>(
                &g_v[(size_t)(b * SEQ + k0) * DMODEL + h * HDIM]);
            #pragma unroll
            for (int i = 0; i < 16; i++) {
                const int f = i * 64 + threadIdx.x;        // [0,1024)
                const int row = f >> 4, c = f & 15;
                const size_t src = (size_t)row * (DMODEL / 4) + c;
                *reinterpret_cast<float4*>(&Ks[row][c * 4]) = kp[src];
                *reinterpret_cast<float4*>(&Vs[row][c * 4]) = vp[src];
            }
        }
        __syncthreads();

        const bool diag = (kt == qt);
        for (int j0 = 0; j0 < 64; j0 += 16) {
            if (diag && j0 > r) break;                  // fully-masked chunk
            float sj[16];
            float cmax = -CUDART_INF_F;
            #pragma unroll
            for (int j = 0; j < 16; j++) {
                const int jj = j0 + j;
                const float4* kr = reinterpret_cast<const float4*>(Ks[jj]);
                float sv = 0.f;
                #pragma unroll
                for (int d4 = 0; d4 < 16; d4++) {
                    float4 kv = kr[d4];
                    sv += qreg[4*d4+0] * kv.x + qreg[4*d4+1] * kv.y
                        + qreg[4*d4+2] * kv.z + qreg[4*d4+3] * kv.w;
                }
                if (diag && jj > r) sv = -CUDART_INF_F; // causal mask
                sj[j] = sv;
                cmax = fmaxf(cmax, sv);
            }
            const float mnew = fmaxf(mval, cmax);
            const float corr = __expf(mval - mnew);     // exp(-inf)=0 first pass
            l *= corr;
            #pragma unroll
            for (int d = 0; d < 64; d++) o[d] *= corr;
            #pragma unroll
            for (int j = 0; j < 16; j++) {
                const int jj = j0 + j;
                const float p = __expf(sj[j] - mnew);
                l += p;
                const float4* vr = reinterpret_cast<const float4*>(Vs[jj]);
                #pragma unroll
                for (int d4 = 0; d4 < 16; d4++) {
                    float4 vv = vr[d4];
                    o[4*d4+0] += p * vv.x; o[4*d4+1] += p * vv.y;
                    o[4*d4+2] += p * vv.z; o[4*d4+3] += p * vv.w;
                }
            }
            mval = mnew;
        }
    }

    const float inv = 1.f / l;
    float4* op = reinterpret_cast<float4*>(
        &g_att[(size_t)(b * SEQ + qrow) * DMODEL + h * HDIM]);
    #pragma unroll
    for (int i = 0; i < 16; i++)
        op[i] = make_float4(o[4*i+0] * inv, o[4*i+1] * inv,
                            o[4*i+2] * inv, o[4*i+3] * inv);
}

// ---------------------------------------------------------------------------
extern "C" void kernel_launch(void* const* d_in, const int* in_sizes, int n_in,
                              void* d_out, int out_size)
{
    const float* x    = (const float*)d_in[0];
    const float* cosp = (const float*)d_in[1];
    const float* sinp = (const float*)d_in[2];
    const float* Wq   = (const float*)d_in[3];
    const float* Wk   = (const float*)d_in[4];
    const float* Wv   = (const float*)d_in[5];
    const float* Wo   = (const float*)d_in[6];
    float* out = (float*)d_out;

    qkv_gemm_kernel<<<dim3(24, 32), 256>>>(x, Wq, Wk, Wv);
    rope_kernel<<<(ROWS * NHEADS * 32) / 256, 256>>>(cosp, sinp);
    attn_kernel<<<dim3(SEQ / 64, BATCH * NHEADS), 64>>>();
    out_gemm_kernel<<<dim3(8, 32), 256>>>(Wo, out);
}